// round 2
// baseline (speedup 1.0000x reference)
#include <cuda_runtime.h>
#include <math.h>

#define N_RNA 4096
#define N_ATAC 8192
#define IN_C 256
#define HID 128
#define THR_S 0.8f

// ---------------- scratch (static device memory; no allocations) ----------------
__device__ float g_Q[N_RNA * HID];
__device__ float g_K[N_ATAC * HID];
__device__ float g_VR[N_RNA * HID];
__device__ float g_VA[N_ATAC * HID];
__device__ float g_AGGR[N_RNA * HID];
__device__ float g_AGGA[N_ATAC * HID];
__device__ float g_CR[N_RNA * 2 * HID];
__device__ float g_CA[N_ATAC * 2 * HID];

// ---------------- batched GEMM: C[m, coff + 0..127] = A[M,K] @ W[K,128] + b ----------------
struct GemmOp {
    const float* A;
    const float* W;
    const float* B;
    float* C;
    int M;
    int K;
    int ldc;
    int coff;
};
struct GemmBatch { GemmOp op[6]; };

__global__ void __launch_bounds__(256) gemm_kernel(GemmBatch batch) {
    const GemmOp op = batch.op[blockIdx.y];
    const int m0 = blockIdx.x * 64;
    if (m0 >= op.M) return;

    __shared__ float a_s[64][33];
    __shared__ float w_s[32][128];

    float acc[8][4];
#pragma unroll
    for (int i = 0; i < 8; ++i) {
        acc[i][0] = 0.f; acc[i][1] = 0.f; acc[i][2] = 0.f; acc[i][3] = 0.f;
    }

    const int t = threadIdx.x;
    const float4* A4 = (const float4*)op.A;
    const float4* W4 = (const float4*)op.W;
    const int Kd4 = op.K >> 2;

    for (int kk = 0; kk < op.K; kk += 32) {
        __syncthreads();
        // stage A tile [64][32] (rows m0..m0+63)
        {
            int k4 = t & 7, r = t >> 3;  // r: 0..31
#pragma unroll
            for (int rr = 0; rr < 2; ++rr) {
                float4 v = A4[(size_t)(m0 + r + rr * 32) * Kd4 + (kk >> 2) + k4];
                a_s[r + rr * 32][k4 * 4 + 0] = v.x;
                a_s[r + rr * 32][k4 * 4 + 1] = v.y;
                a_s[r + rr * 32][k4 * 4 + 2] = v.z;
                a_s[r + rr * 32][k4 * 4 + 3] = v.w;
            }
        }
        // stage W tile [32][128]
        {
#pragma unroll
            for (int p = 0; p < 4; ++p) {
                int idx = t + p * 256;
                int k = idx >> 5, c4 = idx & 31;
                *(float4*)&w_s[k][c4 * 4] = W4[(size_t)(kk + k) * 32 + c4];
            }
        }
        __syncthreads();
#pragma unroll
        for (int k = 0; k < 32; ++k) {
            float4 w4 = *(const float4*)&w_s[k][(t & 31) * 4];
#pragma unroll
            for (int i = 0; i < 8; ++i) {
                float av = a_s[(t >> 5) * 8 + i][k];
                acc[i][0] += av * w4.x;
                acc[i][1] += av * w4.y;
                acc[i][2] += av * w4.z;
                acc[i][3] += av * w4.w;
            }
        }
    }

    const int c = (t & 31) * 4;
    const int rb = (t >> 5) * 8;
    float4 b4 = *(const float4*)&op.B[c];
#pragma unroll
    for (int i = 0; i < 8; ++i) {
        size_t row = (size_t)(m0 + rb + i);
        float4 o;
        o.x = acc[i][0] + b4.x;
        o.y = acc[i][1] + b4.y;
        o.z = acc[i][2] + b4.z;
        o.w = acc[i][3] + b4.w;
        *(float4*)&op.C[row * op.ldc + op.coff + c] = o;
    }
}

// ---------------- fused attention: logits + exact top-10 + threshold + sparse agg ----------------
// Tile: 16 rna rows x (2 heads) per block, streamed over a in chunks of 128.
// Smem layout (dynamic, 99456 B):
//   q_s : float4[32][17]   (d4-major, padded)         8704 B
//   k_s : float4[32][129]  (d4-major, padded)        66048 B
//   m_s : float [16][128]                              8192 B
//   l_s : float [32][129]  (masked logits, padded)   16512 B
// After the main loop, k_s is dead and overlaid with top-k merge buffers.

__device__ __forceinline__ bool tk_better(float v, int i, float v2, int i2) {
    // jax top_k order: larger value first, ties -> lower index first
    return (v > v2) || (v == v2 && i < i2);
}

__device__ __forceinline__ void tk_insert(float* bv, int* bi, float v, int gi) {
    // caller guarantees tk_better(v, gi, bv[9], bi[9])
    bool done = false;
#pragma unroll
    for (int k = 9; k > 0; --k) {
        if (!done) {
            if (tk_better(v, gi, bv[k - 1], bi[k - 1])) {
                bv[k] = bv[k - 1];
                bi[k] = bi[k - 1];
            } else {
                bv[k] = v;
                bi[k] = gi;
                done = true;
            }
        }
    }
    if (!done) { bv[0] = v; bi[0] = gi; }
}

__global__ void __launch_bounds__(128) attn_kernel(const float* __restrict__ mask) {
    extern __shared__ char smraw[];
    float4* q_s = (float4*)smraw;                                  // [32][17]
    float4* k_s = (float4*)(smraw + 32 * 17 * sizeof(float4));     // [32][129]
    float* m_s = (float*)(smraw + (32 * 17 + 32 * 129) * sizeof(float4));  // [16][128]
    float* l_s = m_s + 16 * 128;                                   // [32][129]
    // overlays on k_s (used after main loop only)
    float* tv = (float*)k_s;            // [32*4*10]
    int* ti = (int*)(tv + 1280);        // [32*4*10]
    float* wv = (float*)(ti + 1280);    // [32*10]
    int* wi = (int*)(wv + 320);         // [32*10]

    const int t = threadIdx.x;
    const int r0 = blockIdx.x * 16;

    // load Q tile, d4-major
    {
        int d4 = t & 31, rl = t >> 5;
        const float4* Q4 = (const float4*)g_Q;
#pragma unroll
        for (int j = 0; j < 4; ++j) {
            int r = rl + j * 4;
            q_s[d4 * 17 + r] = Q4[(size_t)(r0 + r) * 32 + d4];
        }
    }

    // per-thread running top-10 over its (row, a-quarter) slice
    float bv[10];
    int bi[10];
#pragma unroll
    for (int k = 0; k < 10; ++k) { bv[k] = -1e30f; bi[k] = 0x7fffffff; }

    const int ag = t & 15;          // a-lane (compute phase)
    const int hh = (t >> 4) & 1;    // head  (compute phase)
    const int rg = t >> 5;          // r-group (compute phase)
    const int row = t & 31;         // row = r_local*2 + h (topk phase)
    const int sub = t >> 5;         // a-quarter (topk phase)

    for (int c = 0; c < N_ATAC / 128; ++c) {
        const int a0 = c * 128;
        __syncthreads();  // k_s reads of prev compute, l_s reads of prev topk done
        // stage K chunk, d4-major
        {
            int d4 = t & 31, al = t >> 5;
            const float4* K4 = (const float4*)g_K;
#pragma unroll 8
            for (int j = 0; j < 32; ++j) {
                int a = al + j * 4;
                k_s[d4 * 129 + a] = K4[(size_t)(a0 + a) * 32 + d4];
            }
        }
        // stage mask tile [16][128]
        {
            int k4 = t & 7, rl = t >> 3;
            const float4* M4 = (const float4*)mask;
            float4* ms4 = (float4*)m_s;
#pragma unroll
            for (int j = 0; j < 4; ++j)
                ms4[rl * 32 + k4 + j * 8] =
                    M4[(size_t)(r0 + rl) * 2048 + (a0 >> 2) + k4 + j * 8];
        }
        __syncthreads();

        // compute 4r x 8a logits per thread (one head)
        float acc[4][8];
#pragma unroll
        for (int i = 0; i < 4; ++i)
#pragma unroll
            for (int j = 0; j < 8; ++j) acc[i][j] = 0.f;

#pragma unroll
        for (int dd = 0; dd < 16; ++dd) {
            int d4 = hh * 16 + dd;
            float4 kf[8];
#pragma unroll
            for (int j = 0; j < 8; ++j) kf[j] = k_s[d4 * 129 + ag + j * 16];
#pragma unroll
            for (int i = 0; i < 4; ++i) {
                float4 qf = q_s[d4 * 17 + rg * 4 + i];
#pragma unroll
                for (int j = 0; j < 8; ++j) {
                    acc[i][j] += qf.x * kf[j].x;
                    acc[i][j] += qf.y * kf[j].y;
                    acc[i][j] += qf.z * kf[j].z;
                    acc[i][j] += qf.w * kf[j].w;
                }
            }
        }

        // write masked logits (sigmoid is monotone -> rank on logits)
#pragma unroll
        for (int i = 0; i < 4; ++i) {
            int r = rg * 4 + i;
#pragma unroll
            for (int j = 0; j < 8; ++j) {
                int a = ag + j * 16;
                l_s[(r * 2 + hh) * 129 + a] = acc[i][j] * m_s[r * 128 + a];
            }
        }
        __syncthreads();

        // top-k scan: each thread scans 32 a's of its row
        for (int ii = 0; ii < 32; ++ii) {
            int a = sub * 32 + ii;
            float v = l_s[row * 129 + a];
            int gi = a0 + a;
            if (tk_better(v, gi, bv[9], bi[9])) tk_insert(bv, bi, v, gi);
        }
    }

    // dump per-thread lists into overlay (k_s is dead; l_s untouched by these writes)
#pragma unroll
    for (int k = 0; k < 10; ++k) {
        tv[(row * 4 + sub) * 10 + k] = bv[k];
        ti[(row * 4 + sub) * 10 + k] = bi[k];
    }
    __syncthreads();

    // merge 4 partial lists per row -> final top-10 -> sigmoid/softmax/threshold weights
    if (t < 32) {
        float fv[10];
        int fi[10];
#pragma unroll
        for (int k = 0; k < 10; ++k) { fv[k] = -1e30f; fi[k] = 0x7fffffff; }
        for (int s = 0; s < 4; ++s)
            for (int k = 0; k < 10; ++k) {
                float v = tv[(t * 4 + s) * 10 + k];
                int gi = ti[(t * 4 + s) * 10 + k];
                if (tk_better(v, gi, fv[9], fi[9])) tk_insert(fv, fi, v, gi);
            }
        float sig[10];
#pragma unroll
        for (int k = 0; k < 10; ++k) sig[k] = 1.f / (1.f + expf(-fv[k]));
        float e[10];
        float den = 0.f;
#pragma unroll
        for (int k = 0; k < 10; ++k) { e[k] = expf(sig[k] - sig[0]); den += e[k]; }
        float inv = 1.f / den;
#pragma unroll
        for (int k = 0; k < 10; ++k) {
            float w = e[k] * inv;
            if (!(sig[k] > THR_S)) w = 0.f;
            wv[t * 10 + k] = w;
            wi[t * 10 + k] = fi[k];
        }
    }
    __syncthreads();

    // sparse aggregation: rna gather (direct) + atac scatter (atomic)
    {
        int d = t & 63, g = t >> 6;  // 64 lanes per d-group, 2 groups
        for (int rr = g; rr < 32; rr += 2) {
            int rloc = rr >> 1, h = rr & 1;
            int r = r0 + rloc;
            float vr = g_VR[(size_t)r * 128 + h * 64 + d];
            float accO = 0.f;
#pragma unroll
            for (int k = 0; k < 10; ++k) {
                float w = wv[rr * 10 + k];
                int a = wi[rr * 10 + k];
                if (w != 0.f) {
                    accO += w * g_VA[(size_t)a * 128 + h * 64 + d];
                    atomicAdd(&g_AGGA[(size_t)a * 128 + h * 64 + d], w * vr);
                }
            }
            g_AGGR[(size_t)r * 128 + h * 64 + d] = accO;
        }
    }
}

// ---------------- launch ----------------
extern "C" void kernel_launch(void* const* d_in, const int* in_sizes, int n_in,
                              void* d_out, int out_size) {
    const float* x_rna = (const float*)d_in[0];
    const float* x_atac = (const float*)d_in[1];
    const float* chrom_mask = (const float*)d_in[2];
    const float* Wq = (const float*)d_in[3];
    const float* bq = (const float*)d_in[4];
    const float* Wk = (const float*)d_in[5];
    const float* bk = (const float*)d_in[6];
    const float* Wvr = (const float*)d_in[7];
    const float* bvr = (const float*)d_in[8];
    const float* Wva = (const float*)d_in[9];
    const float* bva = (const float*)d_in[10];
    const float* Wor = (const float*)d_in[11];
    const float* bor = (const float*)d_in[12];
    const float* Woa = (const float*)d_in[13];
    const float* boa = (const float*)d_in[14];
    const float* Wsr = (const float*)d_in[15];
    const float* bsr = (const float*)d_in[16];
    const float* Wsa = (const float*)d_in[17];
    const float* bsa = (const float*)d_in[18];
    const float* Wdr = (const float*)d_in[19];
    const float* bdr = (const float*)d_in[20];
    const float* Wda = (const float*)d_in[21];
    const float* bda = (const float*)d_in[22];
    float* out = (float*)d_out;

    float *Qp, *Kp, *VRp, *VAp, *AGGRp, *AGGAp, *CRp, *CAp;
    cudaGetSymbolAddress((void**)&Qp, g_Q);
    cudaGetSymbolAddress((void**)&Kp, g_K);
    cudaGetSymbolAddress((void**)&VRp, g_VR);
    cudaGetSymbolAddress((void**)&VAp, g_VA);
    cudaGetSymbolAddress((void**)&AGGRp, g_AGGR);
    cudaGetSymbolAddress((void**)&AGGAp, g_AGGA);
    cudaGetSymbolAddress((void**)&CRp, g_CR);
    cudaGetSymbolAddress((void**)&CAp, g_CA);

    cudaMemsetAsync(AGGAp, 0, (size_t)N_ATAC * HID * sizeof(float));

    // batch 1: all input projections (Wsr/Wsa write straight into concat halves)
    GemmBatch b1 = {};
    b1.op[0] = {x_rna, Wq, bq, Qp, N_RNA, IN_C, 128, 0};
    b1.op[1] = {x_atac, Wk, bk, Kp, N_ATAC, IN_C, 128, 0};
    b1.op[2] = {x_rna, Wvr, bvr, VRp, N_RNA, IN_C, 128, 0};
    b1.op[3] = {x_atac, Wva, bva, VAp, N_ATAC, IN_C, 128, 0};
    b1.op[4] = {x_rna, Wsr, bsr, CRp, N_RNA, IN_C, 256, 128};
    b1.op[5] = {x_atac, Wsa, bsa, CAp, N_ATAC, IN_C, 256, 128};
    gemm_kernel<<<dim3(128, 6), 256>>>(b1);

    // fused attention
    cudaFuncSetAttribute(attn_kernel, cudaFuncAttributeMaxDynamicSharedMemorySize, 99456);
    attn_kernel<<<N_RNA / 16, 128, 99456>>>(chrom_mask);

    // batch 2: out-projections into concat first halves
    GemmBatch b2 = {};
    b2.op[0] = {AGGRp, Wor, bor, CRp, N_RNA, HID, 256, 0};
    b2.op[1] = {AGGAp, Woa, boa, CAp, N_ATAC, HID, 256, 0};
    gemm_kernel<<<dim3(128, 2), 256>>>(b2);

    // batch 3: dim-reduction GEMMs into d_out (rna first, then atac)
    GemmBatch b3 = {};
    b3.op[0] = {CRp, Wdr, bdr, out, N_RNA, 2 * HID, 128, 0};
    b3.op[1] = {CAp, Wda, bda, out + (size_t)N_RNA * HID, N_ATAC, 2 * HID, 128, 0};
    gemm_kernel<<<dim3(128, 2), 256>>>(b3);
}